// round 6
// baseline (speedup 1.0000x reference)
#include <cuda_runtime.h>
#include <cuda_fp16.h>
#include <cstdint>
#include <math.h>

// Problem constants
#define PP    16
#define EE    512
#define HH    512
#define NTOT  8192

// Tiling
#define MT       128   // rows per CTA
#define NCHW     256   // N chunk width (2 chunks per 512-wide layer)
#define KCH      32    // K chunk (halves) streamed per stage
#define THREADS  256   // 8 warps: 2 (M) x 4 (N), warp tile 64x64

#define ASTRIDE  1040  // bytes per A row: 512 halves + 16B pad
#define BSTRIDE  80    // bytes per B row: 32 halves + 16B pad

#define SA     0
#define SB     (MT * ASTRIDE)              // 133120
#define SBSZ   (NCHW * BSTRIDE)            // 20480
#define SBIAS  (SB + 3 * SBSZ)             // 194560 (3 B buffers)
#define SRED   (SBIAS + 3 * 2048)          // 200704
#define SMEM_BYTES (SRED + MT * 4 * 4)     // 202752

// Static device scratch (no runtime allocation)
__device__ __align__(16) __half g_e[(size_t)NTOT * EE];        // e, fp16
__device__ __align__(16) __half g_w0t[(size_t)PP * HH * EE];   // W0^T [p][h_out][e]
__device__ __align__(16) __half g_w1t[(size_t)PP * HH * HH];   // W1^T [p][h_out][h_in]
__device__ __align__(16) __half g_h[(size_t)PP * NTOT * HH];   // hidden scratch

// ---------------------------------------------------------------------------
// Base-ISA PTX helpers
// ---------------------------------------------------------------------------
__device__ __forceinline__ uint32_t smem_u32(const void* p) {
    uint32_t a;
    asm("{ .reg .u64 t; cvta.to.shared.u64 t, %1; cvt.u32.u64 %0, t; }"
        : "=r"(a) : "l"(p));
    return a;
}
__device__ __forceinline__ void cp16(uint32_t dst, const void* src) {
    asm volatile("cp.async.cg.shared.global [%0], [%1], 16;" :: "r"(dst), "l"(src));
}
__device__ __forceinline__ void cp_commit() { asm volatile("cp.async.commit_group;" ::: "memory"); }
template <int N>
__device__ __forceinline__ void cp_wait() { asm volatile("cp.async.wait_group %0;" :: "n"(N) : "memory"); }

__device__ __forceinline__ void ldm4(uint32_t* r, uint32_t a) {
    asm volatile("ldmatrix.sync.aligned.m8n8.x4.shared.b16 {%0,%1,%2,%3}, [%4];"
                 : "=r"(r[0]), "=r"(r[1]), "=r"(r[2]), "=r"(r[3]) : "r"(a));
}
// fp16-accumulate HMMA (2x rate vs f32-acc on sm_103 -- the hypothesis under test)
__device__ __forceinline__ void mma16816h(uint32_t* c, const uint32_t* a, const uint32_t* b) {
    asm volatile(
        "mma.sync.aligned.m16n8k16.row.col.f16.f16.f16.f16 "
        "{%0,%1}, {%2,%3,%4,%5}, {%6,%7}, {%0,%1};"
        : "+r"(c[0]), "+r"(c[1])
        : "r"(a[0]), "r"(a[1]), "r"(a[2]), "r"(a[3]), "r"(b[0]), "r"(b[1]));
}

// ---------------------------------------------------------------------------
// Pre-pass kernels
// ---------------------------------------------------------------------------
__global__ void conv_e_kernel(const float* __restrict__ e) {
    int i = blockIdx.x * blockDim.x + threadIdx.x;
    float4 v = ((const float4*)e)[i];
    __half2 a = __floats2half2_rn(v.x, v.y);
    __half2 b = __floats2half2_rn(v.z, v.w);
    uint2 pk;
    pk.x = *(uint32_t*)&a;
    pk.y = *(uint32_t*)&b;
    ((uint2*)g_e)[i] = pk;
}

__global__ void conv_wt_kernel(const float* __restrict__ W, int which) {
    __shared__ float tile[32][33];
    __half* Wt = which ? g_w1t : g_w0t;
    int p = blockIdx.z;
    const float* w = W + (size_t)p * 512 * 512;
    __half* wt = Wt + (size_t)p * 512 * 512;
    int c0 = blockIdx.x * 32, r0 = blockIdx.y * 32;
    for (int j = threadIdx.y; j < 32; j += 8)
        tile[j][threadIdx.x] = w[(size_t)(r0 + j) * 512 + c0 + threadIdx.x];
    __syncthreads();
    for (int j = threadIdx.y; j < 32; j += 8)
        wt[(size_t)(c0 + j) * 512 + r0 + threadIdx.x] = __float2half(tile[threadIdx.x][j]);
}

// ---------------------------------------------------------------------------
// Fused MLP kernel: 8 warps, 64x64 warp tiles, f16-acc HMMA + split-K f32 promote
// ---------------------------------------------------------------------------
__global__ void __launch_bounds__(THREADS, 1)
mlp_fused(const float* __restrict__ b0, const float* __restrict__ b1,
          const float* __restrict__ W2, const float* __restrict__ b2,
          float* __restrict__ out) {
    extern __shared__ char smem[];
    uint32_t sb = smem_u32(smem);
    int tid = threadIdx.x;
    int lane = tid & 31, wid = tid >> 5;
    int wm = wid & 1;        // 0..1, 64 rows each
    int wn = wid >> 1;       // 0..3, 64 cols each
    int p = blockIdx.x >> 6; // consecutive CTAs share a partition -> L2 weight reuse
    int mt = blockIdx.x & 63;
    int m0 = mt * MT;

    float* b0s = (float*)(smem + SBIAS);
    float* b1s = (float*)(smem + SBIAS + 2048);
    float* w2s = (float*)(smem + SBIAS + 4096);
    for (int j = tid; j < 512; j += THREADS) {
        b0s[j] = b0[p * 512 + j];
        b1s[j] = b1[p * 512 + j];
        w2s[j] = W2[p * 512 + j];
    }

    // Load A = e tile [128 x 512 halves] into padded smem via cp.async
    for (int i = tid; i < MT * 64; i += THREADS) {
        int row = i >> 6, c = i & 63;
        cp16(sb + SA + row * ASTRIDE + c * 16, g_e + ((size_t)(m0 + row)) * EE + c * 8);
    }
    cp_commit();
    cp_wait<0>();
    __syncthreads();

    // ldmatrix lane-address components
    int selA = lane >> 3;
    int a_row  = (selA & 1) * 8 + (lane & 7);
    int a_koff = (selA >> 1) * 8;
    int b_row  = (lane >> 4) * 8 + (lane & 7);
    int b_koff = ((lane >> 3) & 1) * 8;

    float pacc[4][2] = {{0.f,0.f},{0.f,0.f},{0.f,0.f},{0.f,0.f}};

#pragma unroll 1
    for (int layer = 0; layer < 2; layer++) {
        const __half* Wt = (layer == 0) ? (g_w0t + (size_t)p * HH * EE)
                                        : (g_w1t + (size_t)p * HH * HH);
        float* bias = (layer == 0) ? b0s : b1s;

#pragma unroll 1
        for (int nch = 0; nch < 2; nch++) {
            __syncthreads();  // close previous chunk's compute before reusing buffers

            // preload kc=0 -> buf0, kc=1 -> buf1
#pragma unroll 1
            for (int pre = 0; pre < 2; pre++) {
                for (int i = tid; i < NCHW * 4; i += THREADS) {
                    int r = i >> 2, c = i & 3;
                    cp16(sb + SB + pre * SBSZ + r * BSTRIDE + c * 16,
                         Wt + ((size_t)(nch * NCHW + r)) * 512 + pre * KCH + c * 8);
                }
                cp_commit();
            }

            float facc[4][8][4];     // fp32 master accumulators
            uint32_t hacc[4][8][2];  // f16x2 group accumulators
#pragma unroll
            for (int mf = 0; mf < 4; mf++)
#pragma unroll
                for (int nf = 0; nf < 8; nf++) {
#pragma unroll
                    for (int u = 0; u < 4; u++) facc[mf][nf][u] = 0.f;
                    hacc[mf][nf][0] = 0u; hacc[mf][nf][1] = 0u;
                }

#pragma unroll 1
            for (int kc = 0; kc < 16; kc++) {
                int buf = kc % 3;
                if (kc < 15) cp_wait<1>(); else cp_wait<0>();
                // single barrier: publishes chunk kc AND closes compute of kc-1
                __syncthreads();

                if (kc + 2 < 16) {
                    int nb = (kc + 2) % 3;   // used at kc-1, closed by barrier above
                    for (int i = tid; i < NCHW * 4; i += THREADS) {
                        int r = i >> 2, c = i & 3;
                        cp16(sb + SB + nb * SBSZ + r * BSTRIDE + c * 16,
                             Wt + ((size_t)(nch * NCHW + r)) * 512 + (kc + 2) * KCH + c * 8);
                    }
                    cp_commit();
                }

                uint32_t bbase = sb + SB + buf * SBSZ;
#pragma unroll
                for (int ks = 0; ks < 2; ks++) {
                    int kk = kc * KCH + ks * 16;
                    uint32_t aR[4][4];
#pragma unroll
                    for (int mf = 0; mf < 4; mf++) {
                        int row = wm * 64 + mf * 16 + a_row;
                        ldm4(aR[mf], sb + SA + row * ASTRIDE + (kk + a_koff) * 2);
                    }
                    uint32_t bR[4][4];
#pragma unroll
                    for (int nf2 = 0; nf2 < 4; nf2++) {
                        int n = wn * 64 + nf2 * 16 + b_row;
                        ldm4(bR[nf2], bbase + n * BSTRIDE + (ks * 16 + b_koff) * 2);
                    }
#pragma unroll
                    for (int mf = 0; mf < 4; mf++)
#pragma unroll
                        for (int nf = 0; nf < 8; nf++)
                            mma16816h(hacc[mf][nf], aR[mf], &bR[nf >> 1][(nf & 1) * 2]);
                }

                // split-K promotion: every 2 kc (K=64) fold f16 group into f32 master
                if (kc & 1) {
#pragma unroll
                    for (int mf = 0; mf < 4; mf++)
#pragma unroll
                        for (int nf = 0; nf < 8; nf++) {
                            float2 f0 = __half22float2(*(__half2*)&hacc[mf][nf][0]);
                            float2 f1 = __half22float2(*(__half2*)&hacc[mf][nf][1]);
                            facc[mf][nf][0] += f0.x;
                            facc[mf][nf][1] += f0.y;
                            facc[mf][nf][2] += f1.x;
                            facc[mf][nf][3] += f1.y;
                            hacc[mf][nf][0] = 0u;
                            hacc[mf][nf][1] = 0u;
                        }
                }
            }

            // Epilogue for this N-chunk
            if (layer == 0) {
#pragma unroll
                for (int mf = 0; mf < 4; mf++) {
                    size_t r0 = (size_t)(p * NTOT) + m0 + wm * 64 + mf * 16 + (lane >> 2);
#pragma unroll
                    for (int nf = 0; nf < 8; nf++) {
                        int col = nch * NCHW + wn * 64 + nf * 8 + (lane & 3) * 2;
                        float* c4 = facc[mf][nf];
                        __half2 h0 = __floats2half2_rn(fmaxf(c4[0] + bias[col], 0.f),
                                                       fmaxf(c4[1] + bias[col + 1], 0.f));
                        __half2 h1 = __floats2half2_rn(fmaxf(c4[2] + bias[col], 0.f),
                                                       fmaxf(c4[3] + bias[col + 1], 0.f));
                        *(__half2*)(g_h + r0 * HH + col) = h0;
                        *(__half2*)(g_h + (r0 + 8) * HH + col) = h1;
                    }
                }
            } else {
#pragma unroll
                for (int mf = 0; mf < 4; mf++) {
#pragma unroll
                    for (int nf = 0; nf < 8; nf++) {
                        int col = nch * NCHW + wn * 64 + nf * 8 + (lane & 3) * 2;
                        float* c4 = facc[mf][nf];
                        float w0v = w2s[col], w1v = w2s[col + 1];
                        pacc[mf][0] = fmaf(fmaxf(c4[0] + bias[col], 0.f), w0v,
                                      fmaf(fmaxf(c4[1] + bias[col + 1], 0.f), w1v, pacc[mf][0]));
                        pacc[mf][1] = fmaf(fmaxf(c4[2] + bias[col], 0.f), w0v,
                                      fmaf(fmaxf(c4[3] + bias[col + 1], 0.f), w1v, pacc[mf][1]));
                    }
                }
            }
        }

        if (layer == 0) {
            __syncthreads();   // all g_h writes of this CTA visible
            for (int i = tid; i < MT * 64; i += THREADS) {
                int row = i >> 6, c = i & 63;
                cp16(sb + SA + row * ASTRIDE + c * 16,
                     g_h + ((size_t)(p * NTOT) + m0 + row) * HH + c * 8);
            }
            cp_commit();
            cp_wait<0>();
            __syncthreads();
        }
    }

    // Final reduction: lanes sharing a row, then across the 4 wn groups
    float* red = (float*)(smem + SRED);
#pragma unroll
    for (int mf = 0; mf < 4; mf++)
#pragma unroll
        for (int rp = 0; rp < 2; rp++) {
            float v = pacc[mf][rp];
            v += __shfl_xor_sync(0xffffffffu, v, 1);
            v += __shfl_xor_sync(0xffffffffu, v, 2);
            if ((lane & 3) == 0) {
                int row = wm * 64 + mf * 16 + rp * 8 + (lane >> 2);
                red[row * 4 + wn] = v;
            }
        }
    __syncthreads();
    if (tid < MT) {
        float z = red[tid * 4] + red[tid * 4 + 1] + red[tid * 4 + 2] + red[tid * 4 + 3] + b2[p];
        out[((size_t)(m0 + tid)) * PP + p] = 1.f / (1.f + __expf(-z));
    }
}

// ---------------------------------------------------------------------------
// Launch
// ---------------------------------------------------------------------------
extern "C" void kernel_launch(void* const* d_in, const int* in_sizes, int n_in,
                              void* d_out, int out_size) {
    const float* e  = (const float*)d_in[0];
    const float* W0 = (const float*)d_in[1];
    const float* b0 = (const float*)d_in[2];
    const float* W1 = (const float*)d_in[3];
    const float* b1 = (const float*)d_in[4];
    const float* W2 = (const float*)d_in[5];
    const float* b2 = (const float*)d_in[6];
    float* out = (float*)d_out;

    cudaFuncSetAttribute(mlp_fused, cudaFuncAttributeMaxDynamicSharedMemorySize, SMEM_BYTES);

    conv_e_kernel<<<(NTOT * EE / 4) / 256, 256>>>(e);
    conv_wt_kernel<<<dim3(16, 16, PP), dim3(32, 8)>>>(W0, 0);
    conv_wt_kernel<<<dim3(16, 16, PP), dim3(32, 8)>>>(W1, 1);
    mlp_fused<<<PP * (NTOT / MT), THREADS, SMEM_BYTES>>>(b0, b1, W2, b2, out);
}

// round 7
// speedup vs baseline: 1.3189x; 1.3189x over previous
#include <cuda_runtime.h>
#include <cuda_fp16.h>
#include <cstdint>
#include <math.h>

// Problem constants
#define PP    16
#define EE    512
#define HH    512
#define NTOT  8192

// Tiling: small CTA so 2 CTAs co-reside per SM and cover each other's bubbles
#define MT       64    // rows per CTA
#define NCHW     256   // N chunk width (2 chunks per 512-wide layer)
#define KCH      32    // K chunk (halves) streamed per stage
#define THREADS  128   // 4 warps: 1 (M) x 4 (N), warp tile 64x64

#define ASTRIDE  1040  // bytes per A row: 512 halves + 16B pad
#define BSTRIDE  80    // bytes per B row: 32 halves + 16B pad

#define SA     0
#define SB     (MT * ASTRIDE)              // 66560
#define SBSZ   (NCHW * BSTRIDE)            // 20480
#define SBIAS  (SB + 2 * SBSZ)             // 107520 (2 B buffers)
#define SRED   (SBIAS + 3 * 2048)          // 113664
#define SMEM_BYTES (SRED + MT * 4 * 4)     // 114688  -> 2 CTAs/SM

// Static device scratch (no runtime allocation)
__device__ __align__(16) __half g_e[(size_t)NTOT * EE];        // e, fp16
__device__ __align__(16) __half g_w0t[(size_t)PP * HH * EE];   // W0^T [p][h_out][e]
__device__ __align__(16) __half g_w1t[(size_t)PP * HH * HH];   // W1^T [p][h_out][h_in]
__device__ __align__(16) __half g_h[(size_t)PP * NTOT * HH];   // hidden scratch

// ---------------------------------------------------------------------------
// Base-ISA PTX helpers
// ---------------------------------------------------------------------------
__device__ __forceinline__ uint32_t smem_u32(const void* p) {
    uint32_t a;
    asm("{ .reg .u64 t; cvta.to.shared.u64 t, %1; cvt.u32.u64 %0, t; }"
        : "=r"(a) : "l"(p));
    return a;
}
__device__ __forceinline__ void cp16(uint32_t dst, const void* src) {
    asm volatile("cp.async.cg.shared.global [%0], [%1], 16;" :: "r"(dst), "l"(src));
}
__device__ __forceinline__ void cp_commit() { asm volatile("cp.async.commit_group;" ::: "memory"); }
template <int N>
__device__ __forceinline__ void cp_wait() { asm volatile("cp.async.wait_group %0;" :: "n"(N) : "memory"); }

__device__ __forceinline__ void ldm4(uint32_t* r, uint32_t a) {
    asm volatile("ldmatrix.sync.aligned.m8n8.x4.shared.b16 {%0,%1,%2,%3}, [%4];"
                 : "=r"(r[0]), "=r"(r[1]), "=r"(r[2]), "=r"(r[3]) : "r"(a));
}
__device__ __forceinline__ void mma16816(float* c, const uint32_t* a, const uint32_t* b) {
    asm volatile(
        "mma.sync.aligned.m16n8k16.row.col.f32.f16.f16.f32 "
        "{%0,%1,%2,%3}, {%4,%5,%6,%7}, {%8,%9}, {%0,%1,%2,%3};"
        : "+f"(c[0]), "+f"(c[1]), "+f"(c[2]), "+f"(c[3])
        : "r"(a[0]), "r"(a[1]), "r"(a[2]), "r"(a[3]), "r"(b[0]), "r"(b[1]));
}

// ---------------------------------------------------------------------------
// Pre-pass kernels
// ---------------------------------------------------------------------------
__global__ void conv_e_kernel(const float* __restrict__ e) {
    int i = blockIdx.x * blockDim.x + threadIdx.x;
    float4 v = ((const float4*)e)[i];
    __half2 a = __floats2half2_rn(v.x, v.y);
    __half2 b = __floats2half2_rn(v.z, v.w);
    uint2 pk;
    pk.x = *(uint32_t*)&a;
    pk.y = *(uint32_t*)&b;
    ((uint2*)g_e)[i] = pk;
}

__global__ void conv_wt_kernel(const float* __restrict__ W, int which) {
    __shared__ float tile[32][33];
    __half* Wt = which ? g_w1t : g_w0t;
    int p = blockIdx.z;
    const float* w = W + (size_t)p * 512 * 512;
    __half* wt = Wt + (size_t)p * 512 * 512;
    int c0 = blockIdx.x * 32, r0 = blockIdx.y * 32;
    for (int j = threadIdx.y; j < 32; j += 8)
        tile[j][threadIdx.x] = w[(size_t)(r0 + j) * 512 + c0 + threadIdx.x];
    __syncthreads();
    for (int j = threadIdx.y; j < 32; j += 8)
        wt[(size_t)(c0 + j) * 512 + r0 + threadIdx.x] = __float2half(tile[threadIdx.x][j]);
}

// ---------------------------------------------------------------------------
// Fused MLP kernel: 4 warps, 64x64 warp tiles, 2 CTAs/SM
// ---------------------------------------------------------------------------
__global__ void __launch_bounds__(THREADS, 2)
mlp_fused(const float* __restrict__ b0, const float* __restrict__ b1,
          const float* __restrict__ W2, const float* __restrict__ b2,
          float* __restrict__ out) {
    extern __shared__ char smem[];
    uint32_t sb = smem_u32(smem);
    int tid = threadIdx.x;
    int lane = tid & 31, wid = tid >> 5;
    int wn = wid;            // 0..3, 64 cols each; single 64-row M group
    int p = blockIdx.x >> 7; // 128 M-tiles per partition, consecutive -> L2 reuse
    int mt = blockIdx.x & 127;
    int m0 = mt * MT;

    float* b0s = (float*)(smem + SBIAS);
    float* b1s = (float*)(smem + SBIAS + 2048);
    float* w2s = (float*)(smem + SBIAS + 4096);
    for (int j = tid; j < 512; j += THREADS) {
        b0s[j] = b0[p * 512 + j];
        b1s[j] = b1[p * 512 + j];
        w2s[j] = W2[p * 512 + j];
    }

    // Load A = e tile [64 x 512 halves] into padded smem via cp.async
    for (int i = tid; i < MT * 64; i += THREADS) {
        int row = i >> 6, c = i & 63;
        cp16(sb + SA + row * ASTRIDE + c * 16, g_e + ((size_t)(m0 + row)) * EE + c * 8);
    }
    cp_commit();
    cp_wait<0>();
    __syncthreads();

    // ldmatrix lane-address components
    int selA = lane >> 3;
    int a_row  = (selA & 1) * 8 + (lane & 7);
    int a_koff = (selA >> 1) * 8;
    int b_row  = (lane >> 4) * 8 + (lane & 7);
    int b_koff = ((lane >> 3) & 1) * 8;

    float pacc[4][2] = {{0.f,0.f},{0.f,0.f},{0.f,0.f},{0.f,0.f}};

#pragma unroll 1
    for (int layer = 0; layer < 2; layer++) {
        const __half* Wt = (layer == 0) ? (g_w0t + (size_t)p * HH * EE)
                                        : (g_w1t + (size_t)p * HH * HH);
        float* bias = (layer == 0) ? b0s : b1s;

#pragma unroll 1
        for (int nch = 0; nch < 2; nch++) {
            // prologue: issue kc=0 into buf0 (buf0 is free: last used 2 kc ago)
            for (int i = tid; i < NCHW * 4; i += THREADS) {
                int r = i >> 2, c = i & 3;
                cp16(sb + SB + r * BSTRIDE + c * 16,
                     Wt + ((size_t)(nch * NCHW + r)) * 512 + c * 8);
            }
            cp_commit();

            float acc[4][8][4];
#pragma unroll
            for (int mf = 0; mf < 4; mf++)
#pragma unroll
                for (int nf = 0; nf < 8; nf++)
#pragma unroll
                    for (int u = 0; u < 4; u++) acc[mf][nf][u] = 0.f;

#pragma unroll 1
            for (int kc = 0; kc < 16; kc++) {
                int buf = kc & 1;
                cp_wait<0>();     // chunk kc has landed (issued 1 iter ago)
                __syncthreads();  // publishes kc; closes compute of kc-1

                if (kc + 1 < 16) {
                    int nb = buf ^ 1;   // used at kc-1; closed by barrier above
                    for (int i = tid; i < NCHW * 4; i += THREADS) {
                        int r = i >> 2, c = i & 3;
                        cp16(sb + SB + nb * SBSZ + r * BSTRIDE + c * 16,
                             Wt + ((size_t)(nch * NCHW + r)) * 512 + (kc + 1) * KCH + c * 8);
                    }
                    cp_commit();
                }

                uint32_t bbase = sb + SB + buf * SBSZ;
#pragma unroll
                for (int ks = 0; ks < 2; ks++) {
                    int kk = kc * KCH + ks * 16;
                    uint32_t aR[4][4];
#pragma unroll
                    for (int mf = 0; mf < 4; mf++) {
                        int row = mf * 16 + a_row;
                        ldm4(aR[mf], sb + SA + row * ASTRIDE + (kk + a_koff) * 2);
                    }
                    uint32_t bR[4][4];
#pragma unroll
                    for (int nf2 = 0; nf2 < 4; nf2++) {
                        int n = wn * 64 + nf2 * 16 + b_row;
                        ldm4(bR[nf2], bbase + n * BSTRIDE + (ks * 16 + b_koff) * 2);
                    }
#pragma unroll
                    for (int mf = 0; mf < 4; mf++)
#pragma unroll
                        for (int nf = 0; nf < 8; nf++)
                            mma16816(acc[mf][nf], aR[mf], &bR[nf >> 1][(nf & 1) * 2]);
                }
            }

            // Epilogue for this N-chunk
            if (layer == 0) {
#pragma unroll
                for (int mf = 0; mf < 4; mf++) {
                    size_t r0 = (size_t)(p * NTOT) + m0 + mf * 16 + (lane >> 2);
#pragma unroll
                    for (int nf = 0; nf < 8; nf++) {
                        int col = nch * NCHW + wn * 64 + nf * 8 + (lane & 3) * 2;
                        float* c4 = acc[mf][nf];
                        __half2 h0 = __floats2half2_rn(fmaxf(c4[0] + bias[col], 0.f),
                                                       fmaxf(c4[1] + bias[col + 1], 0.f));
                        __half2 h1 = __floats2half2_rn(fmaxf(c4[2] + bias[col], 0.f),
                                                       fmaxf(c4[3] + bias[col + 1], 0.f));
                        *(__half2*)(g_h + r0 * HH + col) = h0;
                        *(__half2*)(g_h + (r0 + 8) * HH + col) = h1;
                    }
                }
            } else {
#pragma unroll
                for (int mf = 0; mf < 4; mf++) {
#pragma unroll
                    for (int nf = 0; nf < 8; nf++) {
                        int col = nch * NCHW + wn * 64 + nf * 8 + (lane & 3) * 2;
                        float* c4 = acc[mf][nf];
                        float w0v = w2s[col], w1v = w2s[col + 1];
                        pacc[mf][0] = fmaf(fmaxf(c4[0] + bias[col], 0.f), w0v,
                                      fmaf(fmaxf(c4[1] + bias[col + 1], 0.f), w1v, pacc[mf][0]));
                        pacc[mf][1] = fmaf(fmaxf(c4[2] + bias[col], 0.f), w0v,
                                      fmaf(fmaxf(c4[3] + bias[col + 1], 0.f), w1v, pacc[mf][1]));
                    }
                }
            }
        }

        if (layer == 0) {
            __syncthreads();   // all g_h writes of this CTA visible
            for (int i = tid; i < MT * 64; i += THREADS) {
                int row = i >> 6, c = i & 63;
                cp16(sb + SA + row * ASTRIDE + c * 16,
                     g_h + ((size_t)(p * NTOT) + m0 + row) * HH + c * 8);
            }
            cp_commit();
            cp_wait<0>();
            __syncthreads();
        }
    }

    // Final reduction: lanes sharing a row, then across the 4 wn groups
    float* red = (float*)(smem + SRED);
#pragma unroll
    for (int mf = 0; mf < 4; mf++)
#pragma unroll
        for (int rp = 0; rp < 2; rp++) {
            float v = pacc[mf][rp];
            v += __shfl_xor_sync(0xffffffffu, v, 1);
            v += __shfl_xor_sync(0xffffffffu, v, 2);
            if ((lane & 3) == 0) {
                int row = mf * 16 + rp * 8 + (lane >> 2);
                red[row * 4 + wn] = v;
            }
        }
    __syncthreads();
    if (tid < MT) {
        float z = red[tid * 4] + red[tid * 4 + 1] + red[tid * 4 + 2] + red[tid * 4 + 3] + b2[p];
        out[((size_t)(m0 + tid)) * PP + p] = 1.f / (1.f + __expf(-z));
    }
}

// ---------------------------------------------------------------------------
// Launch
// ---------------------------------------------------------------------------
extern "C" void kernel_launch(void* const* d_in, const int* in_sizes, int n_in,
                              void* d_out, int out_size) {
    const float* e  = (const float*)d_in[0];
    const float* W0 = (const float*)d_in[1];
    const float* b0 = (const float*)d_in[2];
    const float* W1 = (const float*)d_in[3];
    const float* b1 = (const float*)d_in[4];
    const float* W2 = (const float*)d_in[5];
    const float* b2 = (const float*)d_in[6];
    float* out = (float*)d_out;

    cudaFuncSetAttribute(mlp_fused, cudaFuncAttributeMaxDynamicSharedMemorySize, SMEM_BYTES);

    conv_e_kernel<<<(NTOT * EE / 4) / 256, 256>>>(e);
    conv_wt_kernel<<<dim3(16, 16, PP), dim3(32, 8)>>>(W0, 0);
    conv_wt_kernel<<<dim3(16, 16, PP), dim3(32, 8)>>>(W1, 1);
    mlp_fused<<<PP * (NTOT / MT), THREADS, SMEM_BYTES>>>(b0, b1, W2, b2, out);
}

// round 8
// speedup vs baseline: 1.4491x; 1.0987x over previous
#include <cuda_runtime.h>
#include <cuda_fp16.h>
#include <cstdint>
#include <math.h>

// Problem constants
#define PP    16
#define EE    512
#define HH    512
#define NTOT  8192

// Tiling: 2 CTAs/SM; warp-private B pipelines (no __syncthreads in mainloop)
#define MT       64    // rows per CTA
#define NCHW     256   // N chunk width (2 chunks per 512-wide layer)
#define KCH      32    // K chunk (halves) per pipeline stage
#define THREADS  128   // 4 warps: 1 (M) x 4 (N), warp tile 64x64

#define ASTRIDE  1040  // bytes per A row: 512 halves + 16B pad
#define BSTRIDE  80    // bytes per B row: 32 halves + 16B pad
#define BBUF     (64 * BSTRIDE)            // 5120: one warp-private chunk buffer
#define BWARP    (2 * BBUF)                // 10240: 2 buffers per warp

#define SA     0
#define SB     (MT * ASTRIDE)              // 66560
#define SBIAS  (SB + 4 * BWARP)            // 107520
#define SRED   (SBIAS + 3 * 2048)          // 113664
#define SMEM_BYTES (SRED + MT * 4 * 4)     // 114688 -> 2 CTAs/SM

// Static device scratch (no runtime allocation)
__device__ __align__(16) __half g_e[(size_t)NTOT * EE];        // e, fp16
__device__ __align__(16) __half g_w0t[(size_t)PP * HH * EE];   // W0^T [p][h_out][e]
__device__ __align__(16) __half g_w1t[(size_t)PP * HH * HH];   // W1^T [p][h_out][h_in]
__device__ __align__(16) __half g_h[(size_t)PP * NTOT * HH];   // hidden scratch

// ---------------------------------------------------------------------------
// Base-ISA PTX helpers
// ---------------------------------------------------------------------------
__device__ __forceinline__ uint32_t smem_u32(const void* p) {
    uint32_t a;
    asm("{ .reg .u64 t; cvta.to.shared.u64 t, %1; cvt.u32.u64 %0, t; }"
        : "=r"(a) : "l"(p));
    return a;
}
__device__ __forceinline__ void cp16(uint32_t dst, const void* src) {
    asm volatile("cp.async.cg.shared.global [%0], [%1], 16;" :: "r"(dst), "l"(src));
}
__device__ __forceinline__ void cp_commit() { asm volatile("cp.async.commit_group;" ::: "memory"); }
template <int N>
__device__ __forceinline__ void cp_wait() { asm volatile("cp.async.wait_group %0;" :: "n"(N) : "memory"); }

__device__ __forceinline__ void ldm4(uint32_t* r, uint32_t a) {
    asm volatile("ldmatrix.sync.aligned.m8n8.x4.shared.b16 {%0,%1,%2,%3}, [%4];"
                 : "=r"(r[0]), "=r"(r[1]), "=r"(r[2]), "=r"(r[3]) : "r"(a));
}
__device__ __forceinline__ void mma16816(float* c, const uint32_t* a, const uint32_t* b) {
    asm volatile(
        "mma.sync.aligned.m16n8k16.row.col.f32.f16.f16.f32 "
        "{%0,%1,%2,%3}, {%4,%5,%6,%7}, {%8,%9}, {%0,%1,%2,%3};"
        : "+f"(c[0]), "+f"(c[1]), "+f"(c[2]), "+f"(c[3])
        : "r"(a[0]), "r"(a[1]), "r"(a[2]), "r"(a[3]), "r"(b[0]), "r"(b[1]));
}

// ---------------------------------------------------------------------------
// Pre-pass kernels
// ---------------------------------------------------------------------------
__global__ void conv_e_kernel(const float* __restrict__ e) {
    int i = blockIdx.x * blockDim.x + threadIdx.x;
    float4 v = ((const float4*)e)[i];
    __half2 a = __floats2half2_rn(v.x, v.y);
    __half2 b = __floats2half2_rn(v.z, v.w);
    uint2 pk;
    pk.x = *(uint32_t*)&a;
    pk.y = *(uint32_t*)&b;
    ((uint2*)g_e)[i] = pk;
}

__global__ void conv_wt_kernel(const float* __restrict__ W, int which) {
    __shared__ float tile[32][33];
    __half* Wt = which ? g_w1t : g_w0t;
    int p = blockIdx.z;
    const float* w = W + (size_t)p * 512 * 512;
    __half* wt = Wt + (size_t)p * 512 * 512;
    int c0 = blockIdx.x * 32, r0 = blockIdx.y * 32;
    for (int j = threadIdx.y; j < 32; j += 8)
        tile[j][threadIdx.x] = w[(size_t)(r0 + j) * 512 + c0 + threadIdx.x];
    __syncthreads();
    for (int j = threadIdx.y; j < 32; j += 8)
        wt[(size_t)(c0 + j) * 512 + r0 + threadIdx.x] = __float2half(tile[threadIdx.x][j]);
}

// ---------------------------------------------------------------------------
// Fused MLP: 4 warps, 64x64 warp tiles, warp-private B double-buffer pipeline
// ---------------------------------------------------------------------------
__global__ void __launch_bounds__(THREADS, 2)
mlp_fused(const float* __restrict__ b0, const float* __restrict__ b1,
          const float* __restrict__ W2, const float* __restrict__ b2,
          float* __restrict__ out) {
    extern __shared__ char smem[];
    uint32_t sb = smem_u32(smem);
    int tid = threadIdx.x;
    int lane = tid & 31, wid = tid >> 5;
    int wn = wid;            // 0..3, 64 cols each; single 64-row M group
    int p = blockIdx.x >> 7; // 128 M-tiles per partition, consecutive -> L2 reuse
    int mt = blockIdx.x & 127;
    int m0 = mt * MT;

    float* b0s = (float*)(smem + SBIAS);
    float* b1s = (float*)(smem + SBIAS + 2048);
    float* w2s = (float*)(smem + SBIAS + 4096);
    for (int j = tid; j < 512; j += THREADS) {
        b0s[j] = b0[p * 512 + j];
        b1s[j] = b1[p * 512 + j];
        w2s[j] = W2[p * 512 + j];
    }

    // Load A = e tile [64 x 512 halves] into padded smem via cp.async
    for (int i = tid; i < MT * 64; i += THREADS) {
        int row = i >> 6, c = i & 63;
        cp16(sb + SA + row * ASTRIDE + c * 16, g_e + ((size_t)(m0 + row)) * EE + c * 8);
    }
    cp_commit();
    cp_wait<0>();
    __syncthreads();

    // ldmatrix lane-address components
    int selA = lane >> 3;
    int a_row  = (selA & 1) * 8 + (lane & 7);
    int a_koff = (selA >> 1) * 8;
    int b_row  = (lane >> 4) * 8 + (lane & 7);
    int b_koff = ((lane >> 3) & 1) * 8;

    uint32_t bw_base = sb + SB + wn * BWARP;  // this warp's private B region
    // per-lane cp.async row/col split for chunk loads (8 x 16B per lane)
    int ld_r = lane >> 2;        // rows handled: ld_r, ld_r+8, ... (8 iters)
    int ld_c = lane & 3;

    float pacc[4][2] = {{0.f,0.f},{0.f,0.f},{0.f,0.f},{0.f,0.f}};

#pragma unroll 1
    for (int layer = 0; layer < 2; layer++) {
        const __half* Wt = (layer == 0) ? (g_w0t + (size_t)p * HH * EE)
                                        : (g_w1t + (size_t)p * HH * HH);
        float* bias = (layer == 0) ? b0s : b1s;

        // Warp-private prologue: issue chunk 0 (nch=0, kc=0)
        {
            const __half* src = Wt + ((size_t)(wn * 64 + ld_r)) * 512 + ld_c * 8;
#pragma unroll
            for (int it = 0; it < 8; it++)
                cp16(bw_base + (ld_r + it * 8) * BSTRIDE + ld_c * 16,
                     src + (size_t)(it * 8) * 512);
            cp_commit();
        }

#pragma unroll 1
        for (int nch = 0; nch < 2; nch++) {
            float acc[4][8][4];
#pragma unroll
            for (int mf = 0; mf < 4; mf++)
#pragma unroll
                for (int nf = 0; nf < 8; nf++)
#pragma unroll
                    for (int u = 0; u < 4; u++) acc[mf][nf][u] = 0.f;

#pragma unroll 1
            for (int kc = 0; kc < 16; kc++) {
                int g = nch * 16 + kc;
                if (g + 1 < 32) {
                    // issue chunk g+1 into the other buffer (its prior user,
                    // chunk g-1, finished compute in the previous iteration)
                    int gn = g + 1;
                    int nc2 = gn >> 4, kc2 = gn & 15;
                    uint32_t bdst = bw_base + (gn & 1) * BBUF;
                    const __half* src = Wt + ((size_t)(nc2 * NCHW + wn * 64 + ld_r)) * 512
                                        + kc2 * KCH + ld_c * 8;
#pragma unroll
                    for (int it = 0; it < 8; it++)
                        cp16(bdst + (ld_r + it * 8) * BSTRIDE + ld_c * 16,
                             src + (size_t)(it * 8) * 512);
                    cp_commit();
                    cp_wait<1>();   // chunk g has landed
                } else {
                    cp_wait<0>();
                }
                __syncwarp();

                uint32_t bbase = bw_base + (g & 1) * BBUF;
#pragma unroll
                for (int ks = 0; ks < 2; ks++) {
                    int kk = kc * KCH + ks * 16;
                    uint32_t aR[4][4];
#pragma unroll
                    for (int mf = 0; mf < 4; mf++) {
                        int row = mf * 16 + a_row;
                        ldm4(aR[mf], sb + SA + row * ASTRIDE + (kk + a_koff) * 2);
                    }
                    uint32_t bR[4][4];
#pragma unroll
                    for (int nf2 = 0; nf2 < 4; nf2++) {
                        int n = nf2 * 16 + b_row;   // row within warp-private tile
                        ldm4(bR[nf2], bbase + n * BSTRIDE + (ks * 16 + b_koff) * 2);
                    }
#pragma unroll
                    for (int mf = 0; mf < 4; mf++)
#pragma unroll
                        for (int nf = 0; nf < 8; nf++)
                            mma16816(acc[mf][nf], aR[mf], &bR[nf >> 1][(nf & 1) * 2]);
                }
                __syncwarp();   // all lanes done with buffer g before next overwrite-issue
            }

            // Epilogue for this N-chunk (prefetch of next chunk already in flight)
            if (layer == 0) {
#pragma unroll
                for (int mf = 0; mf < 4; mf++) {
                    size_t r0 = (size_t)(p * NTOT) + m0 + mf * 16 + (lane >> 2);
#pragma unroll
                    for (int nf = 0; nf < 8; nf++) {
                        int col = nch * NCHW + wn * 64 + nf * 8 + (lane & 3) * 2;
                        float* c4 = acc[mf][nf];
                        __half2 h0 = __floats2half2_rn(fmaxf(c4[0] + bias[col], 0.f),
                                                       fmaxf(c4[1] + bias[col + 1], 0.f));
                        __half2 h1 = __floats2half2_rn(fmaxf(c4[2] + bias[col], 0.f),
                                                       fmaxf(c4[3] + bias[col + 1], 0.f));
                        *(__half2*)(g_h + r0 * HH + col) = h0;
                        *(__half2*)(g_h + (r0 + 8) * HH + col) = h1;
                    }
                }
            } else {
#pragma unroll
                for (int mf = 0; mf < 4; mf++) {
#pragma unroll
                    for (int nf = 0; nf < 8; nf++) {
                        int col = nch * NCHW + wn * 64 + nf * 8 + (lane & 3) * 2;
                        float* c4 = acc[mf][nf];
                        float w0v = w2s[col], w1v = w2s[col + 1];
                        pacc[mf][0] = fmaf(fmaxf(c4[0] + bias[col], 0.f), w0v,
                                      fmaf(fmaxf(c4[1] + bias[col + 1], 0.f), w1v, pacc[mf][0]));
                        pacc[mf][1] = fmaf(fmaxf(c4[2] + bias[col], 0.f), w0v,
                                      fmaf(fmaxf(c4[3] + bias[col + 1], 0.f), w1v, pacc[mf][1]));
                    }
                }
            }
        }

        if (layer == 0) {
            __syncthreads();   // all g_h writes of this CTA visible
            for (int i = tid; i < MT * 64; i += THREADS) {
                int row = i >> 6, c = i & 63;
                cp16(sb + SA + row * ASTRIDE + c * 16,
                     g_h + ((size_t)(p * NTOT) + m0 + row) * HH + c * 8);
            }
            cp_commit();
            cp_wait<0>();
            __syncthreads();
        }
    }

    // Final reduction: lanes sharing a row, then across the 4 wn groups
    float* red = (float*)(smem + SRED);
#pragma unroll
    for (int mf = 0; mf < 4; mf++)
#pragma unroll
        for (int rp = 0; rp < 2; rp++) {
            float v = pacc[mf][rp];
            v += __shfl_xor_sync(0xffffffffu, v, 1);
            v += __shfl_xor_sync(0xffffffffu, v, 2);
            if ((lane & 3) == 0) {
                int row = mf * 16 + rp * 8 + (lane >> 2);
                red[row * 4 + wn] = v;
            }
        }
    __syncthreads();
    if (tid < MT) {
        float z = red[tid * 4] + red[tid * 4 + 1] + red[tid * 4 + 2] + red[tid * 4 + 3] + b2[p];
        out[((size_t)(m0 + tid)) * PP + p] = 1.f / (1.f + __expf(-z));
    }
}

// ---------------------------------------------------------------------------
// Launch
// ---------------------------------------------------------------------------
extern "C" void kernel_launch(void* const* d_in, const int* in_sizes, int n_in,
                              void* d_out, int out_size) {
    const float* e  = (const float*)d_in[0];
    const float* W0 = (const float*)d_in[1];
    const float* b0 = (const float*)d_in[2];
    const float* W1 = (const float*)d_in[3];
    const float* b1 = (const float*)d_in[4];
    const float* W2 = (const float*)d_in[5];
    const float* b2 = (const float*)d_in[6];
    float* out = (float*)d_out;

    cudaFuncSetAttribute(mlp_fused, cudaFuncAttributeMaxDynamicSharedMemorySize, SMEM_BYTES);

    conv_e_kernel<<<(NTOT * EE / 4) / 256, 256>>>(e);
    conv_wt_kernel<<<dim3(16, 16, PP), dim3(32, 8)>>>(W0, 0);
    conv_wt_kernel<<<dim3(16, 16, PP), dim3(32, 8)>>>(W1, 1);
    mlp_fused<<<PP * (NTOT / MT), THREADS, SMEM_BYTES>>>(b0, b1, W2, b2, out);
}

// round 9
// speedup vs baseline: 1.5833x; 1.0926x over previous
#include <cuda_runtime.h>
#include <cuda_fp16.h>
#include <cstdint>
#include <math.h>

// Problem constants
#define PP    16
#define EE    512
#define HH    512
#define NTOT  8192

// Tiling: 2 CTAs/SM; warp-private 3-stage B pipeline; swizzled smem (no pads)
#define MT       64    // rows per CTA
#define THREADS  128   // 4 warps: 1 (M) x 4 (N), warp tile 64x64

#define SA     0                 // A: 64 rows x 1024B, XOR-swizzled
#define SB     65536             // B: 4 warps x 3 bufs x 4096B
#define BBUF   4096
#define BWARP  (3 * BBUF)
#define SMEM_BYTES 114688        // 65536 + 49152 -> 2 CTAs/SM (same as R8)

// Static device scratch (no runtime allocation)
__device__ __align__(16) __half g_e[(size_t)NTOT * EE];        // e, fp16
__device__ __align__(16) __half g_w0t[(size_t)PP * HH * EE];   // W0^T [p][h_out][e]
__device__ __align__(16) __half g_w1t[(size_t)PP * HH * HH];   // W1^T [p][h_out][h_in]
__device__ __align__(16) __half g_h[(size_t)PP * NTOT * HH];   // hidden scratch

// ---------------------------------------------------------------------------
// Base-ISA PTX helpers
// ---------------------------------------------------------------------------
__device__ __forceinline__ uint32_t smem_u32(const void* p) {
    uint32_t a;
    asm("{ .reg .u64 t; cvta.to.shared.u64 t, %1; cvt.u32.u64 %0, t; }"
        : "=r"(a) : "l"(p));
    return a;
}
__device__ __forceinline__ void cp16(uint32_t dst, const void* src) {
    asm volatile("cp.async.cg.shared.global [%0], [%1], 16;" :: "r"(dst), "l"(src));
}
__device__ __forceinline__ void cp_commit() { asm volatile("cp.async.commit_group;" ::: "memory"); }
template <int N>
__device__ __forceinline__ void cp_wait() { asm volatile("cp.async.wait_group %0;" :: "n"(N) : "memory"); }

__device__ __forceinline__ void ldm4(uint32_t* r, uint32_t a) {
    asm volatile("ldmatrix.sync.aligned.m8n8.x4.shared.b16 {%0,%1,%2,%3}, [%4];"
                 : "=r"(r[0]), "=r"(r[1]), "=r"(r[2]), "=r"(r[3]) : "r"(a));
}
__device__ __forceinline__ void mma16816(float* c, const uint32_t* a, const uint32_t* b) {
    asm volatile(
        "mma.sync.aligned.m16n8k16.row.col.f32.f16.f16.f32 "
        "{%0,%1,%2,%3}, {%4,%5,%6,%7}, {%8,%9}, {%0,%1,%2,%3};"
        : "+f"(c[0]), "+f"(c[1]), "+f"(c[2]), "+f"(c[3])
        : "r"(a[0]), "r"(a[1]), "r"(a[2]), "r"(a[3]), "r"(b[0]), "r"(b[1]));
}

// Issue one warp-private B chunk g (layer-local, 0..31) via cp.async
__device__ __forceinline__ void issue_b_chunk(uint32_t bw_base, const __half* __restrict__ Wt,
                                              int g, int wn, int lane) {
    int nc2 = g >> 4, kc2 = g & 15;
    uint32_t bdst = bw_base + (uint32_t)(g % 3) * BBUF;
    int lr0 = lane >> 2, c = lane & 3;
    const __half* src = Wt + ((size_t)(nc2 * 256 + wn * 64 + lr0)) * 512 + kc2 * 32 + c * 8;
#pragma unroll
    for (int it = 0; it < 8; it++) {
        int lr = lr0 + it * 8;
        uint32_t cph = (uint32_t)(c ^ ((lr >> 1) & 3));
        cp16(bdst + (uint32_t)lr * 64 + cph * 16, src + (size_t)(it * 8) * 512);
    }
    cp_commit();
}

// ---------------------------------------------------------------------------
// Pre-pass kernels
// ---------------------------------------------------------------------------
__global__ void conv_e_kernel(const float* __restrict__ e) {
    int i = blockIdx.x * blockDim.x + threadIdx.x;
    float4 v = ((const float4*)e)[i];
    __half2 a = __floats2half2_rn(v.x, v.y);
    __half2 b = __floats2half2_rn(v.z, v.w);
    uint2 pk;
    pk.x = *(uint32_t*)&a;
    pk.y = *(uint32_t*)&b;
    ((uint2*)g_e)[i] = pk;
}

__global__ void conv_wt_kernel(const float* __restrict__ W, int which) {
    __shared__ float tile[32][33];
    __half* Wt = which ? g_w1t : g_w0t;
    int p = blockIdx.z;
    const float* w = W + (size_t)p * 512 * 512;
    __half* wt = Wt + (size_t)p * 512 * 512;
    int c0 = blockIdx.x * 32, r0 = blockIdx.y * 32;
    for (int j = threadIdx.y; j < 32; j += 8)
        tile[j][threadIdx.x] = w[(size_t)(r0 + j) * 512 + c0 + threadIdx.x];
    __syncthreads();
    for (int j = threadIdx.y; j < 32; j += 8)
        wt[(size_t)(c0 + j) * 512 + r0 + threadIdx.x] = __float2half(tile[threadIdx.x][j]);
}

// ---------------------------------------------------------------------------
// Fused MLP: 4 warps, 64x64 warp tiles, warp-private 3-stage B pipeline
// ---------------------------------------------------------------------------
__global__ void __launch_bounds__(THREADS, 2)
mlp_fused(const float* __restrict__ b0, const float* __restrict__ b1,
          const float* __restrict__ W2, const float* __restrict__ b2,
          float* __restrict__ out) {
    extern __shared__ char smem[];
    uint32_t sb = smem_u32(smem);
    int tid = threadIdx.x;
    int lane = tid & 31, wid = tid >> 5;
    int wn = wid;            // 0..3, 64 cols each; single 64-row M group
    int p = blockIdx.x >> 7; // 128 M-tiles per partition, consecutive -> L2 reuse
    int mt = blockIdx.x & 127;
    int m0 = mt * MT;

    // Load A = e tile [64 x 512 halves] into swizzled smem via cp.async
    for (int i = tid; i < MT * 64; i += THREADS) {
        int row = i >> 6, c = i & 63;
        uint32_t cph = (uint32_t)(c ^ (row & 7));
        cp16(sb + SA + (uint32_t)row * 1024 + cph * 16,
             g_e + ((size_t)(m0 + row)) * EE + c * 8);
    }
    cp_commit();
    cp_wait<0>();
    __syncthreads();

    // ldmatrix lane-address components
    int selA = lane >> 3;
    int a_row  = (selA & 1) * 8 + (lane & 7);
    int a_koff = (selA >> 1);            // 0/1: extra 16B chunk in K
    int b_row  = (lane >> 4) * 8 + (lane & 7);
    int b_kchk = (lane >> 3) & 1;        // 0/1: extra 16B chunk in K

    uint32_t bw_base = sb + SB + (uint32_t)wn * BWARP;

    float pacc[4][2] = {{0.f,0.f},{0.f,0.f},{0.f,0.f},{0.f,0.f}};

#pragma unroll 1
    for (int layer = 0; layer < 2; layer++) {
        const __half* Wt = (layer == 0) ? (g_w0t + (size_t)p * HH * EE)
                                        : (g_w1t + (size_t)p * HH * HH);
        const float* bias = (layer == 0) ? (b0 + p * 512) : (b1 + p * 512);
        const float* w2g  = W2 + p * 512;

        // B prologue: chunks 0 and 1 in flight
        issue_b_chunk(bw_base, Wt, 0, wn, lane);
        issue_b_chunk(bw_base, Wt, 1, wn, lane);

#pragma unroll 1
        for (int nch = 0; nch < 2; nch++) {
            float acc[4][8][4];
#pragma unroll
            for (int mf = 0; mf < 4; mf++)
#pragma unroll
                for (int nf = 0; nf < 8; nf++)
#pragma unroll
                    for (int u = 0; u < 4; u++) acc[mf][nf][u] = 0.f;

#pragma unroll 1
            for (int kc = 0; kc < 16; kc++) {
                int g = nch * 16 + kc;
                if (g + 2 < 32) {
                    issue_b_chunk(bw_base, Wt, g + 2, wn, lane);  // overwrites buf of g-1
                    cp_wait<2>();   // chunk g landed
                } else if (g == 30) {
                    cp_wait<1>();
                } else {
                    cp_wait<0>();
                }
                __syncwarp();

                uint32_t bbase = bw_base + (uint32_t)(g % 3) * BBUF;
#pragma unroll
                for (int ks = 0; ks < 2; ks++) {
                    uint32_t aR[4][4];
#pragma unroll
                    for (int mf = 0; mf < 4; mf++) {
                        int row = mf * 16 + a_row;
                        int ca = kc * 4 + ks * 2 + a_koff;          // 16B chunk in A row
                        uint32_t cph = (uint32_t)(ca ^ (row & 7));
                        ldm4(aR[mf], sb + SA + (uint32_t)row * 1024 + cph * 16);
                    }
                    uint32_t bR[4][4];
#pragma unroll
                    for (int nf2 = 0; nf2 < 4; nf2++) {
                        int n = nf2 * 16 + b_row;
                        int cb = ks * 2 + b_kchk;                   // 16B chunk in B row
                        uint32_t cph = (uint32_t)(cb ^ ((n >> 1) & 3));
                        ldm4(bR[nf2], bbase + (uint32_t)n * 64 + cph * 16);
                    }
#pragma unroll
                    for (int mf = 0; mf < 4; mf++)
#pragma unroll
                        for (int nf = 0; nf < 8; nf++)
                            mma16816(acc[mf][nf], aR[mf], &bR[nf >> 1][(nf & 1) * 2]);
                }
            }

            // Epilogue for this N-chunk (bias via LDG; next chunk prefetch in flight)
            if (layer == 0) {
#pragma unroll
                for (int mf = 0; mf < 4; mf++) {
                    size_t r0 = (size_t)(p * NTOT) + m0 + mf * 16 + (lane >> 2);
#pragma unroll
                    for (int nf = 0; nf < 8; nf++) {
                        int col = nch * 256 + wn * 64 + nf * 8 + (lane & 3) * 2;
                        float2 bv = *(const float2*)(bias + col);
                        float* c4 = acc[mf][nf];
                        __half2 h0 = __floats2half2_rn(fmaxf(c4[0] + bv.x, 0.f),
                                                       fmaxf(c4[1] + bv.y, 0.f));
                        __half2 h1 = __floats2half2_rn(fmaxf(c4[2] + bv.x, 0.f),
                                                       fmaxf(c4[3] + bv.y, 0.f));
                        *(__half2*)(g_h + r0 * HH + col) = h0;
                        *(__half2*)(g_h + (r0 + 8) * HH + col) = h1;
                    }
                }
            } else {
#pragma unroll
                for (int mf = 0; mf < 4; mf++) {
#pragma unroll
                    for (int nf = 0; nf < 8; nf++) {
                        int col = nch * 256 + wn * 64 + nf * 8 + (lane & 3) * 2;
                        float2 bv = *(const float2*)(bias + col);
                        float2 wv = *(const float2*)(w2g + col);
                        float* c4 = acc[mf][nf];
                        pacc[mf][0] = fmaf(fmaxf(c4[0] + bv.x, 0.f), wv.x,
                                      fmaf(fmaxf(c4[1] + bv.y, 0.f), wv.y, pacc[mf][0]));
                        pacc[mf][1] = fmaf(fmaxf(c4[2] + bv.x, 0.f), wv.x,
                                      fmaf(fmaxf(c4[3] + bv.y, 0.f), wv.y, pacc[mf][1]));
                    }
                }
            }
        }

        if (layer == 0) {
            __syncthreads();   // all g_h writes of this CTA visible, A reads done
            for (int i = tid; i < MT * 64; i += THREADS) {
                int row = i >> 6, c = i & 63;
                uint32_t cph = (uint32_t)(c ^ (row & 7));
                cp16(sb + SA + (uint32_t)row * 1024 + cph * 16,
                     g_h + ((size_t)(p * NTOT) + m0 + row) * HH + c * 8);
            }
            cp_commit();
            cp_wait<0>();
            __syncthreads();
        }
    }

    // Final reduction: red scratch reuses the B region (mainloops done)
    __syncthreads();                 // ensure ALL warps finished their B buffers
    float* red = (float*)(smem + SB);
#pragma unroll
    for (int mf = 0; mf < 4; mf++)
#pragma unroll
        for (int rp = 0; rp < 2; rp++) {
            float v = pacc[mf][rp];
            v += __shfl_xor_sync(0xffffffffu, v, 1);
            v += __shfl_xor_sync(0xffffffffu, v, 2);
            if ((lane & 3) == 0) {
                int row = mf * 16 + rp * 8 + (lane >> 2);
                red[row * 4 + wn] = v;
            }
        }
    __syncthreads();
    if (tid < MT) {
        float z = red[tid * 4] + red[tid * 4 + 1] + red[tid * 4 + 2] + red[tid * 4 + 3] + b2[p];
        out[((size_t)(m0 + tid)) * PP + p] = 1.f / (1.f + __expf(-z));
    }
}

// ---------------------------------------------------------------------------
// Launch
// ---------------------------------------------------------------------------
extern "C" void kernel_launch(void* const* d_in, const int* in_sizes, int n_in,
                              void* d_out, int out_size) {
    const float* e  = (const float*)d_in[0];
    const float* W0 = (const float*)d_in[1];
    const float* b0 = (const float*)d_in[2];
    const float* W1 = (const float*)d_in[3];
    const float* b1 = (const float*)d_in[4];
    const float* W2 = (const float*)d_in[5];
    const float* b2 = (const float*)d_in[6];
    float* out = (float*)d_out;

    cudaFuncSetAttribute(mlp_fused, cudaFuncAttributeMaxDynamicSharedMemorySize, SMEM_BYTES);

    conv_e_kernel<<<(NTOT * EE / 4) / 256, 256>>>(e);
    conv_wt_kernel<<<dim3(16, 16, PP), dim3(32, 8)>>>(W0, 0);
    conv_wt_kernel<<<dim3(16, 16, PP), dim3(32, 8)>>>(W1, 1);
    mlp_fused<<<PP * (NTOT / MT), THREADS, SMEM_BYTES>>>(b0, b1, W2, b2, out);
}

// round 10
// speedup vs baseline: 1.6884x; 1.0664x over previous
#include <cuda_runtime.h>
#include <cuda_fp16.h>
#include <cstdint>
#include <math.h>

// Problem constants
#define PP    16
#define EE    512
#define HH    512
#define NTOT  8192

// Tiling: 2 CTAs/SM; warp-private 3-stage B pipeline; swizzled smem
#define MT       64
#define THREADS  128   // 4 warps: warp tile 64x64

#define SA     0                 // A: 64 rows x 1024B, XOR-swizzled
#define SB     65536             // B: 4 warps x 3 bufs x 4096B
#define BBUF   4096
#define BWARP  (3 * BBUF)
#define SMEM_BYTES 114688        // -> 2 CTAs/SM

// Static device scratch
__device__ __align__(16) __half g_e[(size_t)NTOT * EE];
// Pipeline-order weights: [p][g=0..31][row 0..255][k 0..31] halves
__device__ __align__(16) __half g_w0t[(size_t)PP * HH * EE];
__device__ __align__(16) __half g_w1t[(size_t)PP * HH * HH];
__device__ __align__(16) __half g_h[(size_t)PP * NTOT * 256];  // only low half staged

// ---------------------------------------------------------------------------
// Base-ISA PTX helpers
// ---------------------------------------------------------------------------
__device__ __forceinline__ uint32_t smem_u32(const void* p) {
    uint32_t a;
    asm("{ .reg .u64 t; cvta.to.shared.u64 t, %1; cvt.u32.u64 %0, t; }"
        : "=r"(a) : "l"(p));
    return a;
}
__device__ __forceinline__ void cp16(uint32_t dst, const void* src) {
    asm volatile("cp.async.cg.shared.global [%0], [%1], 16;" :: "r"(dst), "l"(src));
}
__device__ __forceinline__ void cp_commit() { asm volatile("cp.async.commit_group;" ::: "memory"); }
template <int N>
__device__ __forceinline__ void cp_wait() { asm volatile("cp.async.wait_group %0;" :: "n"(N) : "memory"); }

__device__ __forceinline__ void ldm4(uint32_t* r, uint32_t a) {
    asm volatile("ldmatrix.sync.aligned.m8n8.x4.shared.b16 {%0,%1,%2,%3}, [%4];"
                 : "=r"(r[0]), "=r"(r[1]), "=r"(r[2]), "=r"(r[3]) : "r"(a));
}
__device__ __forceinline__ void mma16816(float* c, const uint32_t* a, const uint32_t* b) {
    asm volatile(
        "mma.sync.aligned.m16n8k16.row.col.f32.f16.f16.f32 "
        "{%0,%1,%2,%3}, {%4,%5,%6,%7}, {%8,%9}, {%0,%1,%2,%3};"
        : "+f"(c[0]), "+f"(c[1]), "+f"(c[2]), "+f"(c[3])
        : "r"(a[0]), "r"(a[1]), "r"(a[2]), "r"(a[3]), "r"(b[0]), "r"(b[1]));
}

// Issue one warp-private B chunk g (0..31). wbase = layer weights for partition p
// (byte pointer). lseed/ldst are per-lane constant src/dst offsets.
__device__ __forceinline__ void issue_b_chunk(uint32_t bw_base, const char* wbase,
                                              int g, uint32_t lseed, uint32_t ldst) {
    uint32_t bdst = bw_base + (uint32_t)(g % 3) * BBUF + ldst;
    const char* src = wbase + (size_t)g * 16384 + lseed;
#pragma unroll
    for (int it = 0; it < 8; it++)
        cp16(bdst + it * 512, src + it * 512);
    cp_commit();
}

// ---------------------------------------------------------------------------
// Pre-pass kernels
// ---------------------------------------------------------------------------
__global__ void conv_e_kernel(const float* __restrict__ e) {
    int i = blockIdx.x * blockDim.x + threadIdx.x;
    float4 v = ((const float4*)e)[i];
    __half2 a = __floats2half2_rn(v.x, v.y);
    __half2 b = __floats2half2_rn(v.z, v.w);
    uint2 pk;
    pk.x = *(uint32_t*)&a;
    pk.y = *(uint32_t*)&b;
    ((uint2*)g_e)[i] = pk;
}

// W [p][kin 512][cout 512] fp32 -> pipeline-order fp16:
//   Wt[p][g][n][k],  g = (cout/256)*16 + kin/32,  n = cout%256,  k = kin%32
__global__ void conv_wt_kernel(const float* __restrict__ W, int which) {
    __shared__ float tile[32][33];
    __half* Wt = which ? g_w1t : g_w0t;
    int p = blockIdx.z;
    const float* w = W + (size_t)p * 512 * 512;
    __half* wt = Wt + (size_t)p * 512 * 512;
    int c0 = blockIdx.x * 32;   // cout tile
    int r0 = blockIdx.y * 32;   // kin tile
    for (int j = threadIdx.y; j < 32; j += 8)
        tile[j][threadIdx.x] = w[(size_t)(r0 + j) * 512 + c0 + threadIdx.x];
    __syncthreads();
    int g = (c0 >> 8) * 16 + (r0 >> 5);
    int nloc = c0 & 255;
    for (int jj = threadIdx.y; jj < 32; jj += 8)
        wt[((size_t)g * 256 + nloc + jj) * 32 + threadIdx.x] =
            __float2half(tile[threadIdx.x][jj]);
}

// ---------------------------------------------------------------------------
// Fused MLP: 4 warps, 64x64 warp tiles, warp-private 3-stage B pipeline
// ---------------------------------------------------------------------------
__global__ void __launch_bounds__(THREADS, 2)
mlp_fused(const float* __restrict__ b0, const float* __restrict__ b1,
          const float* __restrict__ W2, const float* __restrict__ b2,
          float* __restrict__ out) {
    extern __shared__ char smem[];
    uint32_t sb = smem_u32(smem);
    int tid = threadIdx.x;
    int lane = tid & 31, wid = tid >> 5;
    int wn = wid;
    int p = blockIdx.x >> 7;
    int mt = blockIdx.x & 127;
    int m0 = mt * MT;

    // Load A = e tile [64 x 512 halves] (swizzled)
    for (int i = tid; i < MT * 64; i += THREADS) {
        int row = i >> 6, c = i & 63;
        uint32_t cph = (uint32_t)(c ^ (row & 7));
        cp16(sb + (uint32_t)row * 1024 + cph * 16,
             g_e + ((size_t)(m0 + row)) * EE + c * 8);
    }
    cp_commit();
    cp_wait<0>();
    __syncthreads();

    // ldmatrix fragment bases (XOR-folded swizzle)
    int selA = lane >> 3;
    int a_row  = (selA & 1) * 8 + (lane & 7);
    int a_koff = (selA >> 1);            // 0/1 -> 16B chunk bit
    int b_row  = (lane >> 4) * 8 + (lane & 7);
    int b_kchk = (lane >> 3) & 1;

    uint32_t aoff[4], boff[4];
#pragma unroll
    for (int mf = 0; mf < 4; mf++) {
        int row = mf * 16 + a_row;
        aoff[mf] = (uint32_t)row * 1024 + (uint32_t)(((row & 7) ^ a_koff) << 4);
    }
#pragma unroll
    for (int nf2 = 0; nf2 < 4; nf2++) {
        int n = nf2 * 16 + b_row;
        boff[nf2] = (uint32_t)n * 64 + (uint32_t)((((n >> 1) & 3) ^ b_kchk) << 4);
    }

    uint32_t bw_base = sb + SB + (uint32_t)wn * BWARP;
    // per-lane constant src/dst offsets for B chunk issue
    uint32_t lseed = (uint32_t)wn * 4096 + (uint32_t)(lane >> 2) * 64 + (uint32_t)(lane & 3) * 16;
    uint32_t ldst  = (uint32_t)(lane >> 2) * 64 +
                     (uint32_t)(((lane & 3) ^ ((lane >> 3) & 3)) << 4);

    const char* w0base = (const char*)(g_w0t + (size_t)p * 512 * 512);
    const char* w1base = (const char*)(g_w1t + (size_t)p * 512 * 512);

    float pacc[4][2] = {{0.f,0.f},{0.f,0.f},{0.f,0.f},{0.f,0.f}};

#pragma unroll 1
    for (int layer = 0; layer < 2; layer++) {
        const char* wcur = (layer == 0) ? w0base : w1base;
        const float* bias = (layer == 0) ? (b0 + p * 512) : (b1 + p * 512);
        const float* w2g  = W2 + p * 512;

        if (layer == 0) {   // layer-1 prologue happens inside the transition
            issue_b_chunk(bw_base, wcur, 0, lseed, ldst);
            issue_b_chunk(bw_base, wcur, 1, lseed, ldst);
        }

#pragma unroll 1
        for (int nch = 0; nch < 2; nch++) {
            float acc[4][8][4];
#pragma unroll
            for (int mf = 0; mf < 4; mf++)
#pragma unroll
                for (int nf = 0; nf < 8; nf++)
#pragma unroll
                    for (int u = 0; u < 4; u++) acc[mf][nf][u] = 0.f;

#pragma unroll 1
            for (int kc = 0; kc < 16; kc++) {
                int g = nch * 16 + kc;
                if (g + 2 < 32) {
                    issue_b_chunk(bw_base, wcur, g + 2, lseed, ldst);
                    cp_wait<2>();
                } else if (g == 30) {
                    cp_wait<1>();
                } else {
                    cp_wait<0>();
                }
                __syncwarp();

                uint32_t bbase = bw_base + (uint32_t)(g % 3) * BBUF;
#pragma unroll
                for (int ks = 0; ks < 2; ks++) {
                    uint32_t kbits = ((uint32_t)kc << 6) ^ ((uint32_t)ks << 5);
                    uint32_t aR[4][4];
#pragma unroll
                    for (int mf = 0; mf < 4; mf++)
                        ldm4(aR[mf], sb + (aoff[mf] ^ kbits));
                    uint32_t bR[4][4];
#pragma unroll
                    for (int nf2 = 0; nf2 < 4; nf2++)
                        ldm4(bR[nf2], bbase + (boff[nf2] ^ ((uint32_t)ks << 5)));
#pragma unroll
                    for (int mf = 0; mf < 4; mf++)
#pragma unroll
                        for (int nf = 0; nf < 8; nf++)
                            mma16816(acc[mf][nf], aR[mf], &bR[nf >> 1][(nf & 1) * 2]);
                }
            }

            // Epilogues
            if (layer == 0 && nch == 0) {
                // h cols 0..255 -> g_h (compact 256-stride)
#pragma unroll
                for (int mf = 0; mf < 4; mf++) {
                    size_t r0 = (size_t)(p * NTOT) + m0 + mf * 16 + (lane >> 2);
#pragma unroll
                    for (int nf = 0; nf < 8; nf++) {
                        int col = wn * 64 + nf * 8 + (lane & 3) * 2;
                        float2 bv = *(const float2*)(bias + col);
                        float* c4 = acc[mf][nf];
                        __half2 h0 = __floats2half2_rn(fmaxf(c4[0] + bv.x, 0.f),
                                                       fmaxf(c4[1] + bv.y, 0.f));
                        __half2 h1 = __floats2half2_rn(fmaxf(c4[2] + bv.x, 0.f),
                                                       fmaxf(c4[3] + bv.y, 0.f));
                        *(__half2*)(g_h + r0 * 256 + col) = h0;
                        *(__half2*)(g_h + (r0 + 8) * 256 + col) = h1;
                    }
                }
            } else if (layer == 0) {
                // Transition: STS h cols 256..511 directly into A; reload cols 0..255
                __syncthreads();   // all warps done reading A (e tile)
                for (int i = tid; i < 64 * 32; i += THREADS) {
                    int row = i >> 5, c = i & 31;
                    uint32_t cph = (uint32_t)(c ^ (row & 7));
                    cp16(sb + (uint32_t)row * 1024 + cph * 16,
                         g_h + ((size_t)(p * NTOT) + m0 + row) * 256 + c * 8);
                }
                cp_commit();
                issue_b_chunk(bw_base, w1base, 0, lseed, ldst);
                issue_b_chunk(bw_base, w1base, 1, lseed, ldst);
                // STS epilogue overlaps the cp.async latency
#pragma unroll
                for (int mf = 0; mf < 4; mf++) {
                    int r = mf * 16 + (lane >> 2);
#pragma unroll
                    for (int nf = 0; nf < 8; nf++) {
                        int col = 256 + wn * 64 + nf * 8 + (lane & 3) * 2;
                        float2 bv = *(const float2*)(bias + col);
                        float* c4 = acc[mf][nf];
                        __half2 h0 = __floats2half2_rn(fmaxf(c4[0] + bv.x, 0.f),
                                                       fmaxf(c4[1] + bv.y, 0.f));
                        __half2 h1 = __floats2half2_rn(fmaxf(c4[2] + bv.x, 0.f),
                                                       fmaxf(c4[3] + bv.y, 0.f));
                        int ca = col >> 3;
                        uint32_t off = (uint32_t)r * 1024 +
                                       (uint32_t)((ca ^ (r & 7)) << 4) +
                                       (uint32_t)(lane & 3) * 4;
                        *(__half2*)(smem + off) = h0;
                        *(__half2*)(smem + off + 8192) = h1;   // row+8: same swizzle phase
                    }
                }
                cp_wait<2>();     // A reload landed (B0,B1 of layer 1 may be pending)
                __syncthreads();
            } else {
                // layer 1: fold into layer-2 dot
#pragma unroll
                for (int mf = 0; mf < 4; mf++) {
#pragma unroll
                    for (int nf = 0; nf < 8; nf++) {
                        int col = nch * 256 + wn * 64 + nf * 8 + (lane & 3) * 2;
                        float2 bv = *(const float2*)(bias + col);
                        float2 wv = *(const float2*)(w2g + col);
                        float* c4 = acc[mf][nf];
                        pacc[mf][0] = fmaf(fmaxf(c4[0] + bv.x, 0.f), wv.x,
                                      fmaf(fmaxf(c4[1] + bv.y, 0.f), wv.y, pacc[mf][0]));
                        pacc[mf][1] = fmaf(fmaxf(c4[2] + bv.x, 0.f), wv.x,
                                      fmaf(fmaxf(c4[3] + bv.y, 0.f), wv.y, pacc[mf][1]));
                    }
                }
            }
        }
    }

    // Final reduction (scratch reuses B region)
    __syncthreads();
    float* red = (float*)(smem + SB);
#pragma unroll
    for (int mf = 0; mf < 4; mf++)
#pragma unroll
        for (int rp = 0; rp < 2; rp++) {
            float v = pacc[mf][rp];
            v += __shfl_xor_sync(0xffffffffu, v, 1);
            v += __shfl_xor_sync(0xffffffffu, v, 2);
            if ((lane & 3) == 0) {
                int row = mf * 16 + rp * 8 + (lane >> 2);
                red[row * 4 + wn] = v;
            }
        }
    __syncthreads();
    if (tid < MT) {
        float z = red[tid * 4] + red[tid * 4 + 1] + red[tid * 4 + 2] + red[tid * 4 + 3] + b2[p];
        out[((size_t)(m0 + tid)) * PP + p] = 1.f / (1.f + __expf(-z));
    }
}

// ---------------------------------------------------------------------------
// Launch
// ---------------------------------------------------------------------------
extern "C" void kernel_launch(void* const* d_in, const int* in_sizes, int n_in,
                              void* d_out, int out_size) {
    const float* e  = (const float*)d_in[0];
    const float* W0 = (const float*)d_in[1];
    const float* b0 = (const float*)d_in[2];
    const float* W1 = (const float*)d_in[3];
    const float* b1 = (const float*)d_in[4];
    const float* W2 = (const float*)d_in[5];
    const float* b2 = (const float*)d_in[6];
    float* out = (float*)d_out;

    cudaFuncSetAttribute(mlp_fused, cudaFuncAttributeMaxDynamicSharedMemorySize, SMEM_BYTES);

    conv_e_kernel<<<(NTOT * EE / 4) / 256, 256>>>(e);
    conv_wt_kernel<<<dim3(16, 16, PP), dim3(32, 8)>>>(W0, 0);
    conv_wt_kernel<<<dim3(16, 16, PP), dim3(32, 8)>>>(W1, 1);
    mlp_fused<<<PP * (NTOT / MT), THREADS, SMEM_BYTES>>>(b0, b1, W2, b2, out);
}

// round 11
// speedup vs baseline: 1.7630x; 1.0442x over previous
#include <cuda_runtime.h>
#include <cuda_fp16.h>
#include <cstdint>
#include <math.h>

// Problem constants
#define PP    16
#define EE    512
#define HH    512
#define NTOT  8192

// Tiling: 2 CTAs/SM; warp-private 3-stage B pipeline; swizzled smem
#define MT       64
#define THREADS  128   // 4 warps: warp tile 64x64

#define SA     0                 // A: 64 rows x 1024B, XOR-swizzled
#define SB     65536             // B: 4 warps x 3 bufs x 4096B
#define BBUF   4096
#define BWARP  (3 * BBUF)
#define SMEM_BYTES 114688        // -> 2 CTAs/SM

// Static device scratch
__device__ __align__(16) __half g_e[(size_t)NTOT * EE];
// Pipeline-order weights: [p][g=0..31][row 0..255][k 0..31] halves
__device__ __align__(16) __half g_w0t[(size_t)PP * HH * EE];
__device__ __align__(16) __half g_w1t[(size_t)PP * HH * HH];
__device__ __align__(16) __half g_h[(size_t)PP * NTOT * 256];  // only low half staged

// ---------------------------------------------------------------------------
// Base-ISA PTX helpers
// ---------------------------------------------------------------------------
__device__ __forceinline__ uint32_t smem_u32(const void* p) {
    uint32_t a;
    asm("{ .reg .u64 t; cvta.to.shared.u64 t, %1; cvt.u32.u64 %0, t; }"
        : "=r"(a) : "l"(p));
    return a;
}
__device__ __forceinline__ void cp16(uint32_t dst, const void* src) {
    asm volatile("cp.async.cg.shared.global [%0], [%1], 16;" :: "r"(dst), "l"(src));
}
__device__ __forceinline__ void cp_commit() { asm volatile("cp.async.commit_group;" ::: "memory"); }
template <int N>
__device__ __forceinline__ void cp_wait() { asm volatile("cp.async.wait_group %0;" :: "n"(N) : "memory"); }

__device__ __forceinline__ void ldm4(uint32_t* r, uint32_t a) {
    asm volatile("ldmatrix.sync.aligned.m8n8.x4.shared.b16 {%0,%1,%2,%3}, [%4];"
                 : "=r"(r[0]), "=r"(r[1]), "=r"(r[2]), "=r"(r[3]) : "r"(a));
}
__device__ __forceinline__ void mma16816(float* c, const uint32_t* a, const uint32_t* b) {
    asm volatile(
        "mma.sync.aligned.m16n8k16.row.col.f32.f16.f16.f32 "
        "{%0,%1,%2,%3}, {%4,%5,%6,%7}, {%8,%9}, {%0,%1,%2,%3};"
        : "+f"(c[0]), "+f"(c[1]), "+f"(c[2]), "+f"(c[3])
        : "r"(a[0]), "r"(a[1]), "r"(a[2]), "r"(a[3]), "r"(b[0]), "r"(b[1]));
}

// Issue one warp-private B chunk g (0..31), contiguous 4KB slab per warp
__device__ __forceinline__ void issue_b_chunk(uint32_t bw_base, const char* wbase,
                                              int g, uint32_t lseed, uint32_t ldst) {
    uint32_t bdst = bw_base + (uint32_t)(g % 3) * BBUF + ldst;
    const char* src = wbase + (size_t)g * 16384 + lseed;
#pragma unroll
    for (int it = 0; it < 8; it++)
        cp16(bdst + it * 512, src + it * 512);
    cp_commit();
}

// One K-chunk of MMAs (64 HMMA) against buffer g
__device__ __forceinline__ void compute_chunk(float (*acc)[8][4], uint32_t sbA,
                                              uint32_t bbase, const uint32_t* aoff,
                                              const uint32_t* boff, int kc) {
#pragma unroll
    for (int ks = 0; ks < 2; ks++) {
        uint32_t kbits = ((uint32_t)kc << 6) ^ ((uint32_t)ks << 5);
        uint32_t aR[4][4];
#pragma unroll
        for (int mf = 0; mf < 4; mf++)
            ldm4(aR[mf], sbA + (aoff[mf] ^ kbits));
        uint32_t bR[4][4];
#pragma unroll
        for (int nf2 = 0; nf2 < 4; nf2++)
            ldm4(bR[nf2], bbase + (boff[nf2] ^ ((uint32_t)ks << 5)));
#pragma unroll
        for (int mf = 0; mf < 4; mf++)
#pragma unroll
            for (int nf = 0; nf < 8; nf++)
                mma16816(acc[mf][nf], aR[mf], &bR[nf >> 1][(nf & 1) * 2]);
    }
}

// ---------------------------------------------------------------------------
// Pre-pass kernels
// ---------------------------------------------------------------------------
__global__ void conv_e_kernel(const float* __restrict__ e) {
    int i = blockIdx.x * blockDim.x + threadIdx.x;
    float4 v = ((const float4*)e)[i];
    __half2 a = __floats2half2_rn(v.x, v.y);
    __half2 b = __floats2half2_rn(v.z, v.w);
    uint2 pk;
    pk.x = *(uint32_t*)&a;
    pk.y = *(uint32_t*)&b;
    ((uint2*)g_e)[i] = pk;
}

// Both weights in one launch. W [p][kin][cout] fp32 -> Wt[p][g][n][k] fp16,
//   g = (cout/256)*16 + kin/32, n = cout%256, k = kin%32
__global__ void conv_w_kernel(const float* __restrict__ W0f,
                              const float* __restrict__ W1f) {
    __shared__ float tile[32][33];
    int which = blockIdx.z >> 4;
    int p = blockIdx.z & 15;
    const float* w = (which ? W1f : W0f) + (size_t)p * 512 * 512;
    __half* wt = (which ? g_w1t : g_w0t) + (size_t)p * 512 * 512;
    int c0 = blockIdx.x * 32;   // cout tile
    int r0 = blockIdx.y * 32;   // kin tile
    for (int j = threadIdx.y; j < 32; j += 8)
        tile[j][threadIdx.x] = w[(size_t)(r0 + j) * 512 + c0 + threadIdx.x];
    __syncthreads();
    int g = (c0 >> 8) * 16 + (r0 >> 5);
    int nloc = c0 & 255;
    for (int jj = threadIdx.y; jj < 32; jj += 8)
        wt[((size_t)g * 256 + nloc + jj) * 32 + threadIdx.x] =
            __float2half(tile[threadIdx.x][jj]);
}

// ---------------------------------------------------------------------------
// Fused MLP: 4 warps, 64x64 warp tiles, warp-private 3-stage B pipeline
// ---------------------------------------------------------------------------
__global__ void __launch_bounds__(THREADS, 2)
mlp_fused(const float* __restrict__ b0, const float* __restrict__ b1,
          const float* __restrict__ W2, const float* __restrict__ b2,
          float* __restrict__ out) {
    extern __shared__ char smem[];
    uint32_t sb = smem_u32(smem);
    int tid = threadIdx.x;
    int lane = tid & 31, wid = tid >> 5;
    int wn = wid;
    int p = blockIdx.x >> 7;
    int mt = blockIdx.x & 127;
    int m0 = mt * MT;

    // lane constants
    int selA = lane >> 3;
    int a_row  = (selA & 1) * 8 + (lane & 7);
    int a_koff = (selA >> 1);
    int b_row  = (lane >> 4) * 8 + (lane & 7);
    int b_kchk = (lane >> 3) & 1;

    uint32_t aoff[4], boff[4];
#pragma unroll
    for (int mf = 0; mf < 4; mf++) {
        int row = mf * 16 + a_row;
        aoff[mf] = (uint32_t)row * 1024 + (uint32_t)(((row & 7) ^ a_koff) << 4);
    }
#pragma unroll
    for (int nf2 = 0; nf2 < 4; nf2++) {
        int n = nf2 * 16 + b_row;
        boff[nf2] = (uint32_t)n * 64 + (uint32_t)((((n >> 1) & 3) ^ b_kchk) << 4);
    }

    uint32_t bw_base = sb + SB + (uint32_t)wn * BWARP;
    uint32_t lseed = (uint32_t)wn * 4096 + (uint32_t)(lane >> 2) * 64 + (uint32_t)(lane & 3) * 16;
    uint32_t ldst  = (uint32_t)(lane >> 2) * 64 +
                     (uint32_t)(((lane & 3) ^ ((lane >> 3) & 3)) << 4);

    const char* w0base = (const char*)(g_w0t + (size_t)p * 512 * 512);
    const char* w1base = (const char*)(g_w1t + (size_t)p * 512 * 512);

    // Prologue: A-tile cp (1 group), then layer-0 B0/B1 -- overlapped
    for (int i = tid; i < MT * 64; i += THREADS) {
        int row = i >> 6, c = i & 63;
        uint32_t cph = (uint32_t)(c ^ (row & 7));
        cp16(sb + (uint32_t)row * 1024 + cph * 16,
             g_e + ((size_t)(m0 + row)) * EE + c * 8);
    }
    cp_commit();
    issue_b_chunk(bw_base, w0base, 0, lseed, ldst);
    issue_b_chunk(bw_base, w0base, 1, lseed, ldst);
    cp_wait<2>();     // A landed; B0/B1 may still be in flight
    __syncthreads();

    float pacc[4][2] = {{0.f,0.f},{0.f,0.f},{0.f,0.f},{0.f,0.f}};

#pragma unroll 1
    for (int layer = 0; layer < 2; layer++) {
        const char* wcur = (layer == 0) ? w0base : w1base;
        const float* bias = (layer == 0) ? (b0 + p * 512) : (b1 + p * 512);
        const float* w2g  = W2 + p * 512;

#pragma unroll 1
        for (int nch = 0; nch < 2; nch++) {
            float acc[4][8][4];
#pragma unroll
            for (int mf = 0; mf < 4; mf++)
#pragma unroll
                for (int nf = 0; nf < 8; nf++)
#pragma unroll
                    for (int u = 0; u < 4; u++) acc[mf][nf][u] = 0.f;

            if (nch == 0) {
                // steady state: always issue g+2, constant wait depth
#pragma unroll 1
                for (int kc = 0; kc < 16; kc++) {
                    issue_b_chunk(bw_base, wcur, kc + 2, lseed, ldst);
                    cp_wait<2>();
                    __syncwarp();
                    compute_chunk(acc, sb, bw_base + (uint32_t)(kc % 3) * BBUF,
                                  aoff, boff, kc);
                }
            } else {
#pragma unroll 1
                for (int kc = 0; kc < 14; kc++) {
                    issue_b_chunk(bw_base, wcur, kc + 18, lseed, ldst);
                    cp_wait<2>();
                    __syncwarp();
                    compute_chunk(acc, sb, bw_base + (uint32_t)((kc + 16) % 3) * BBUF,
                                  aoff, boff, kc);
                }
                cp_wait<1>(); __syncwarp();
                compute_chunk(acc, sb, bw_base + (uint32_t)(30 % 3) * BBUF, aoff, boff, 14);
                cp_wait<0>(); __syncwarp();
                compute_chunk(acc, sb, bw_base + (uint32_t)(31 % 3) * BBUF, aoff, boff, 15);
            }

            // Epilogues
            if (layer == 0 && nch == 0) {
#pragma unroll
                for (int mf = 0; mf < 4; mf++) {
                    size_t r0 = (size_t)(p * NTOT) + m0 + mf * 16 + (lane >> 2);
#pragma unroll
                    for (int nf = 0; nf < 8; nf++) {
                        int col = wn * 64 + nf * 8 + (lane & 3) * 2;
                        float2 bv = *(const float2*)(bias + col);
                        float* c4 = acc[mf][nf];
                        __half2 h0 = __floats2half2_rn(fmaxf(c4[0] + bv.x, 0.f),
                                                       fmaxf(c4[1] + bv.y, 0.f));
                        __half2 h1 = __floats2half2_rn(fmaxf(c4[2] + bv.x, 0.f),
                                                       fmaxf(c4[3] + bv.y, 0.f));
                        *(__half2*)(g_h + r0 * 256 + col) = h0;
                        *(__half2*)(g_h + (r0 + 8) * 256 + col) = h1;
                    }
                }
            } else if (layer == 0) {
                // Transition: STS h cols 256..511 into A; reload cols 0..255; prime layer-1 B
                __syncthreads();
                for (int i = tid; i < 64 * 32; i += THREADS) {
                    int row = i >> 5, c = i & 31;
                    uint32_t cph = (uint32_t)(c ^ (row & 7));
                    cp16(sb + (uint32_t)row * 1024 + cph * 16,
                         g_h + ((size_t)(p * NTOT) + m0 + row) * 256 + c * 8);
                }
                cp_commit();
                issue_b_chunk(bw_base, w1base, 0, lseed, ldst);
                issue_b_chunk(bw_base, w1base, 1, lseed, ldst);
#pragma unroll
                for (int mf = 0; mf < 4; mf++) {
                    int r = mf * 16 + (lane >> 2);
#pragma unroll
                    for (int nf = 0; nf < 8; nf++) {
                        int col = 256 + wn * 64 + nf * 8 + (lane & 3) * 2;
                        float2 bv = *(const float2*)(bias + col);
                        float* c4 = acc[mf][nf];
                        __half2 h0 = __floats2half2_rn(fmaxf(c4[0] + bv.x, 0.f),
                                                       fmaxf(c4[1] + bv.y, 0.f));
                        __half2 h1 = __floats2half2_rn(fmaxf(c4[2] + bv.x, 0.f),
                                                       fmaxf(c4[3] + bv.y, 0.f));
                        int ca = col >> 3;
                        uint32_t off = (uint32_t)r * 1024 +
                                       (uint32_t)((ca ^ (r & 7)) << 4) +
                                       (uint32_t)(lane & 3) * 4;
                        *(__half2*)(smem + off) = h0;
                        *(__half2*)(smem + off + 8192) = h1;   // row+8: same swizzle phase
                    }
                }
                cp_wait<2>();     // A reload landed
                __syncthreads();
            } else {
                // layer 1: fold into layer-2 dot
#pragma unroll
                for (int mf = 0; mf < 4; mf++) {
#pragma unroll
                    for (int nf = 0; nf < 8; nf++) {
                        int col = nch * 256 + wn * 64 + nf * 8 + (lane & 3) * 2;
                        float2 bv = *(const float2*)(bias + col);
                        float2 wv = *(const float2*)(w2g + col);
                        float* c4 = acc[mf][nf];
                        pacc[mf][0] = fmaf(fmaxf(c4[0] + bv.x, 0.f), wv.x,
                                      fmaf(fmaxf(c4[1] + bv.y, 0.f), wv.y, pacc[mf][0]));
                        pacc[mf][1] = fmaf(fmaxf(c4[2] + bv.x, 0.f), wv.x,
                                      fmaf(fmaxf(c4[3] + bv.y, 0.f), wv.y, pacc[mf][1]));
                    }
                }
            }
        }
    }

    // Final reduction (scratch reuses B region)
    __syncthreads();
    float* red = (float*)(smem + SB);
#pragma unroll
    for (int mf = 0; mf < 4; mf++)
#pragma unroll
        for (int rp = 0; rp < 2; rp++) {
            float v = pacc[mf][rp];
            v += __shfl_xor_sync(0xffffffffu, v, 1);
            v += __shfl_xor_sync(0xffffffffu, v, 2);
            if ((lane & 3) == 0) {
                int row = mf * 16 + rp * 8 + (lane >> 2);
                red[row * 4 + wn] = v;
            }
        }
    __syncthreads();
    if (tid < MT) {
        float z = red[tid * 4] + red[tid * 4 + 1] + red[tid * 4 + 2] + red[tid * 4 + 3] + b2[p];
        out[((size_t)(m0 + tid)) * PP + p] = 1.f / (1.f + __expf(-z));
    }
}

// ---------------------------------------------------------------------------
// Launch
// ---------------------------------------------------------------------------
extern "C" void kernel_launch(void* const* d_in, const int* in_sizes, int n_in,
                              void* d_out, int out_size) {
    const float* e  = (const float*)d_in[0];
    const float* W0 = (const float*)d_in[1];
    const float* b0 = (const float*)d_in[2];
    const float* W1 = (const float*)d_in[3];
    const float* b1 = (const float*)d_in[4];
    const float* W2 = (const float*)d_in[5];
    const float* b2 = (const float*)d_in[6];
    float* out = (float*)d_out;

    cudaFuncSetAttribute(mlp_fused, cudaFuncAttributeMaxDynamicSharedMemorySize, SMEM_BYTES);

    conv_e_kernel<<<(NTOT * EE / 4) / 256, 256>>>(e);
    conv_w_kernel<<<dim3(16, 16, 32), dim3(32, 8)>>>(W0, W1);
    mlp_fused<<<PP * (NTOT / MT), THREADS, SMEM_BYTES>>>(b0, b1, W2, b2, out);
}